// round 2
// baseline (speedup 1.0000x reference)
#include <cuda_runtime.h>
#include <math.h>

#define B_ 4
#define N_ 4096
#define M_ 1024
#define C_ 384
#define H_ 8
#define HD_ 48

// Scratch (allocation-free rule: __device__ globals)
__device__ float g_q [B_ * (size_t)N_ * C_];       // q projection  [B,N,384]
__device__ float g_kv[B_ * (size_t)M_ * 2 * C_];   // kv projection [B,M,768] = [B,M,2,H,48]
__device__ float g_x [B_ * (size_t)N_ * C_];       // attention out [B,N,384]

// ---------------------------------------------------------------------------
// Tiled fp32 GEMM: C[M,N] = A[M,K] @ B[K,N]  (+ bias[n] + res[m,n] if EPI)
// BM=BN=64, BK=16, 256 threads, 4x4 micro-tile per thread.
// Requires M%64==0, N%64==0, K%16==0 (true for all three calls).
// ---------------------------------------------------------------------------
template <bool EPI>
__global__ __launch_bounds__(256) void gemm64_kernel(
    const float* __restrict__ A, const float* __restrict__ Bm,
    float* __restrict__ C, int M, int N, int K,
    const float* __restrict__ bias, const float* __restrict__ res)
{
    const int BM = 64, BN = 64, BK = 16;
    __shared__ __align__(16) float As[BK][BM];   // A transposed: As[k][m]
    __shared__ __align__(16) float Bs[BK][BN];   // Bs[k][n]

    const int tid = threadIdx.x;
    const int tx = tid & 15;        // 0..15  -> 4 cols each
    const int ty = tid >> 4;        // 0..15  -> 4 rows each
    const int rowBase = blockIdx.y * BM;
    const int colBase = blockIdx.x * BN;

    float acc[4][4] = {};

    for (int k0 = 0; k0 < K; k0 += BK) {
        // Load A tile (64x16), coalesced over k
        #pragma unroll
        for (int i = 0; i < 4; i++) {
            int idx = tid + i * 256;
            int r = idx >> 4, c = idx & 15;
            As[c][r] = A[(size_t)(rowBase + r) * K + (k0 + c)];
        }
        // Load B tile (16x64), coalesced over n
        #pragma unroll
        for (int i = 0; i < 4; i++) {
            int idx = tid + i * 256;
            int r = idx >> 6, c = idx & 63;
            Bs[r][c] = Bm[(size_t)(k0 + r) * N + (colBase + c)];
        }
        __syncthreads();

        #pragma unroll
        for (int kk = 0; kk < BK; kk++) {
            float4 a4 = *reinterpret_cast<const float4*>(&As[kk][ty * 4]);
            float4 b4 = *reinterpret_cast<const float4*>(&Bs[kk][tx * 4]);
            float af[4] = {a4.x, a4.y, a4.z, a4.w};
            float bf[4] = {b4.x, b4.y, b4.z, b4.w};
            #pragma unroll
            for (int i = 0; i < 4; i++)
                #pragma unroll
                for (int j = 0; j < 4; j++)
                    acc[i][j] = fmaf(af[i], bf[j], acc[i][j]);
        }
        __syncthreads();
    }

    #pragma unroll
    for (int i = 0; i < 4; i++) {
        const int row = rowBase + ty * 4 + i;
        const int col = colBase + tx * 4;
        float4 v = make_float4(acc[i][0], acc[i][1], acc[i][2], acc[i][3]);
        if (EPI) {
            float4 bz = *reinterpret_cast<const float4*>(&bias[col]);
            float4 rz = *reinterpret_cast<const float4*>(&res[(size_t)row * N + col]);
            v.x += bz.x + rz.x; v.y += bz.y + rz.y;
            v.z += bz.z + rz.z; v.w += bz.w + rz.w;
        }
        *reinterpret_cast<float4*>(&C[(size_t)row * N + col]) = v;
    }
}

// ---------------------------------------------------------------------------
// Flash-style attention, fp32 SIMT.
// grid = (N/128, H, B), block = 128 threads. Thread t owns query row
// n = blockIdx.x*128 + t. q vector + accumulator in registers; K/V tiles of
// 32 rows in shared memory (broadcast reads in the dot loops).
// ---------------------------------------------------------------------------
__global__ __launch_bounds__(128, 1) void attn_kernel(
    const float* __restrict__ q, const float* __restrict__ kv,
    float* __restrict__ x)
{
    const int QB = 128, MB = 32;
    __shared__ __align__(16) float sK[MB][HD_];
    __shared__ __align__(16) float sV[MB][HD_];

    const int b = blockIdx.z;
    const int h = blockIdx.y;
    const int n = blockIdx.x * QB + threadIdx.x;
    const float scale = 0.144337567297406441127f;  // 48^-0.5

    float qv[HD_];
    const float* qp = q + ((size_t)(b * N_ + n)) * C_ + h * HD_;
    #pragma unroll
    for (int d = 0; d < HD_; d++) qv[d] = qp[d];

    float mrun = -1e30f, l = 0.0f;
    float acc[HD_] = {};

    for (int m0 = 0; m0 < M_; m0 += MB) {
        // Cooperative load of K,V chunk: MB*48 = 1536 floats each
        for (int idx = threadIdx.x; idx < MB * HD_; idx += QB) {
            int j = idx / HD_;
            int d = idx - j * HD_;
            size_t base = ((size_t)(b * M_ + m0 + j) * 2) * C_ + h * HD_ + d;
            sK[j][d] = kv[base];
            sV[j][d] = kv[base + C_];
        }
        __syncthreads();

        #pragma unroll 2
        for (int j = 0; j < MB; j++) {
            float s = 0.0f;
            #pragma unroll
            for (int d = 0; d < HD_; d++) s = fmaf(qv[d], sK[j][d], s);
            s *= scale;
            if (s > mrun) {                       // rare after warmup
                float corr = __expf(mrun - s);
                l *= corr;
                #pragma unroll
                for (int d = 0; d < HD_; d++) acc[d] *= corr;
                mrun = s;
            }
            float p = __expf(s - mrun);
            l += p;
            #pragma unroll
            for (int d = 0; d < HD_; d++) acc[d] = fmaf(p, sV[j][d], acc[d]);
        }
        __syncthreads();
    }

    const float inv = 1.0f / l;
    float* xp = x + ((size_t)(b * N_ + n)) * C_ + h * HD_;
    #pragma unroll
    for (int d = 0; d < HD_; d++) xp[d] = acc[d] * inv;
}

// ---------------------------------------------------------------------------
// Launch
// ---------------------------------------------------------------------------
extern "C" void kernel_launch(void* const* d_in, const int* in_sizes, int n_in,
                              void* d_out, int out_size)
{
    const float* q_x   = (const float*)d_in[0];  // [4,4096,384]
    const float* kv_x  = (const float*)d_in[1];  // [4,1024,384]
    const float* Wq    = (const float*)d_in[2];  // [384,384]
    const float* Wkv   = (const float*)d_in[3];  // [384,768]
    const float* Wproj = (const float*)d_in[4];  // [384,384]
    const float* bproj = (const float*)d_in[5];  // [384]
    float* out = (float*)d_out;                  // [4,4096,384]

    float *gq, *gkv, *gx;
    cudaGetSymbolAddress((void**)&gq,  g_q);
    cudaGetSymbolAddress((void**)&gkv, g_kv);
    cudaGetSymbolAddress((void**)&gx,  g_x);

    // 1) q = q_x @ Wq          [16384,384] = [16384,384] @ [384,384]
    gemm64_kernel<false><<<dim3(C_ / 64, (B_ * N_) / 64), 256>>>(
        q_x, Wq, gq, B_ * N_, C_, C_, nullptr, nullptr);

    // 2) kv = kv_x @ Wkv       [4096,768] = [4096,384] @ [384,768]
    gemm64_kernel<false><<<dim3((2 * C_) / 64, (B_ * M_) / 64), 256>>>(
        kv_x, Wkv, gkv, B_ * M_, 2 * C_, C_, nullptr, nullptr);

    // 3) attention -> g_x [B,N,384]
    attn_kernel<<<dim3(N_ / 128, H_, B_), 128>>>(gq, gkv, gx);

    // 4) out = g_x @ Wproj + bproj + g_q
    gemm64_kernel<true><<<dim3(C_ / 64, (B_ * N_) / 64), 256>>>(
        gx, Wproj, out, B_ * N_, C_, C_, bproj, gq);
}

// round 3
// speedup vs baseline: 1.3069x; 1.3069x over previous
#include <cuda_runtime.h>
#include <math.h>

#define B_ 4
#define N_ 4096
#define M_ 1024
#define C_ 384
#define H_ 8
#define HD_ 48
#define HD2_ 24   // head_dim in float2

// Scratch (allocation-free rule: __device__ globals)
__device__ float g_q [B_ * (size_t)N_ * C_];       // q projection  [B,N,384]
__device__ float g_kv[B_ * (size_t)M_ * 2 * C_];   // kv projection [B,M,2,384]
__device__ float g_x [B_ * (size_t)N_ * C_];       // attention out [B,N,384]

// ---------------------------------------------------------------------------
// Packed fp32x2 FMA (sm_100+): emits FFMA2 — 2x fp32 throughput on fma pipe.
// ---------------------------------------------------------------------------
__device__ __forceinline__ float2 ffma2(float2 a, float2 b, float2 c) {
    unsigned long long au, bu, cu, du;
    au = *reinterpret_cast<unsigned long long*>(&a);
    bu = *reinterpret_cast<unsigned long long*>(&b);
    cu = *reinterpret_cast<unsigned long long*>(&c);
    asm("fma.rn.f32x2 %0, %1, %2, %3;" : "=l"(du) : "l"(au), "l"(bu), "l"(cu));
    return *reinterpret_cast<float2*>(&du);
}

// ---------------------------------------------------------------------------
// SGEMM: C[M,N] = A[M,K] @ B[K,N] (+ bias[n] + res[m,n] if EPI)
// BM=BN=128, BK=8, 256 threads, 8x8 micro-tile, FFMA2 inner product,
// register-prefetch pipelining. Requires M%128==0, N%128==0, K%8==0.
// ---------------------------------------------------------------------------
template <bool EPI>
__global__ __launch_bounds__(256) void sgemm128_kernel(
    const float* __restrict__ A, const float* __restrict__ Bm,
    float* __restrict__ C, int M, int N, int K,
    const float* __restrict__ bias, const float* __restrict__ res)
{
    const int BM = 128, BN = 128, BK = 8;
    __shared__ __align__(16) float As[BK][BM];
    __shared__ __align__(16) float Bs[BK][BN];

    const int tid = threadIdx.x;
    const int tx = tid & 15;          // 0..15 -> 8 cols each
    const int ty = tid >> 4;          // 0..15 -> 8 rows each
    const int rowBase = blockIdx.y * BM;
    const int colBase = blockIdx.x * BN;

    // global load mapping
    const int arow = tid >> 1;            // 0..127
    const int acol = (tid & 1) * 4;       // 0 or 4
    const int brow = tid >> 5;            // 0..7
    const int bcol = (tid & 31) * 4;      // 0..124

    const float* Aptr = A + (size_t)(rowBase + arow) * K + acol;
    const float* Bptr = Bm + (size_t)brow * N + colBase + bcol;

    float4 aReg = *reinterpret_cast<const float4*>(Aptr);
    float4 bReg = *reinterpret_cast<const float4*>(Bptr);

    float2 acc[8][4];
    #pragma unroll
    for (int i = 0; i < 8; i++)
        #pragma unroll
        for (int j = 0; j < 4; j++) acc[i][j] = make_float2(0.f, 0.f);

    for (int k0 = 0; k0 < K; k0 += BK) {
        __syncthreads();   // previous compute done before overwrite
        As[acol + 0][arow] = aReg.x;
        As[acol + 1][arow] = aReg.y;
        As[acol + 2][arow] = aReg.z;
        As[acol + 3][arow] = aReg.w;
        *reinterpret_cast<float4*>(&Bs[brow][bcol]) = bReg;
        __syncthreads();

        if (k0 + BK < K) {   // prefetch next tile
            aReg = *reinterpret_cast<const float4*>(Aptr + k0 + BK);
            bReg = *reinterpret_cast<const float4*>(Bptr + (size_t)(k0 + BK) * N);
        }

        #pragma unroll
        for (int kk = 0; kk < BK; kk++) {
            float4 a0 = *reinterpret_cast<const float4*>(&As[kk][ty * 8]);
            float4 a1 = *reinterpret_cast<const float4*>(&As[kk][ty * 8 + 4]);
            float4 b0 = *reinterpret_cast<const float4*>(&Bs[kk][tx * 8]);
            float4 b1 = *reinterpret_cast<const float4*>(&Bs[kk][tx * 8 + 4]);
            float av[8] = {a0.x, a0.y, a0.z, a0.w, a1.x, a1.y, a1.z, a1.w};
            float2 bv[4] = {make_float2(b0.x, b0.y), make_float2(b0.z, b0.w),
                            make_float2(b1.x, b1.y), make_float2(b1.z, b1.w)};
            #pragma unroll
            for (int i = 0; i < 8; i++) {
                float2 ad = make_float2(av[i], av[i]);
                #pragma unroll
                for (int j = 0; j < 4; j++)
                    acc[i][j] = ffma2(ad, bv[j], acc[i][j]);
            }
        }
    }

    #pragma unroll
    for (int i = 0; i < 8; i++) {
        const int row = rowBase + ty * 8 + i;
        const int col = colBase + tx * 8;
        float4 v0 = make_float4(acc[i][0].x, acc[i][0].y, acc[i][1].x, acc[i][1].y);
        float4 v1 = make_float4(acc[i][2].x, acc[i][2].y, acc[i][3].x, acc[i][3].y);
        if (EPI) {
            float4 bz0 = *reinterpret_cast<const float4*>(&bias[col]);
            float4 bz1 = *reinterpret_cast<const float4*>(&bias[col + 4]);
            float4 rz0 = *reinterpret_cast<const float4*>(&res[(size_t)row * N + col]);
            float4 rz1 = *reinterpret_cast<const float4*>(&res[(size_t)row * N + col + 4]);
            v0.x += bz0.x + rz0.x; v0.y += bz0.y + rz0.y;
            v0.z += bz0.z + rz0.z; v0.w += bz0.w + rz0.w;
            v1.x += bz1.x + rz1.x; v1.y += bz1.y + rz1.y;
            v1.z += bz1.z + rz1.z; v1.w += bz1.w + rz1.w;
        }
        *reinterpret_cast<float4*>(&C[(size_t)row * N + col]) = v0;
        *reinterpret_cast<float4*>(&C[(size_t)row * N + col + 4]) = v1;
    }
}

// ---------------------------------------------------------------------------
// Flash-style attention, packed fp32x2 math.
// grid = (N/128, H, B), block = 128. Thread t owns query row n.
// q pre-scaled by scale*log2(e) so p = exp2f(s - m) directly.
// ---------------------------------------------------------------------------
__global__ void attn_kernel(
    const float* __restrict__ q, const float* __restrict__ kv,
    float* __restrict__ x)
{
    const int QB = 128, MB = 32;
    __shared__ __align__(16) float2 sK[MB][HD2_];
    __shared__ __align__(16) float2 sV[MB][HD2_];

    const int b = blockIdx.z;
    const int h = blockIdx.y;
    const int n = blockIdx.x * QB + threadIdx.x;
    const float qscale = 0.144337567297406441127f * 1.44269504088896340736f; // 48^-.5 * log2(e)

    float2 qv[HD2_];
    const float2* qp = reinterpret_cast<const float2*>(
        q + ((size_t)(b * N_ + n)) * C_ + h * HD_);
    #pragma unroll
    for (int d = 0; d < HD2_; d++) {
        float2 t = qp[d];
        qv[d] = make_float2(t.x * qscale, t.y * qscale);
    }

    float mrun = -1e30f, l = 0.0f;
    float2 acc[HD2_];
    #pragma unroll
    for (int d = 0; d < HD2_; d++) acc[d] = make_float2(0.f, 0.f);

    for (int m0 = 0; m0 < M_; m0 += MB) {
        // Cooperative load: MB*24 float2 each for K and V
        for (int idx = threadIdx.x; idx < MB * HD2_; idx += QB) {
            int j = idx / HD2_;
            int d = idx - j * HD2_;
            const float2* base = reinterpret_cast<const float2*>(
                kv + ((size_t)(b * M_ + m0 + j) * 2) * C_ + h * HD_) + d;
            sK[j][d] = base[0];
            sV[j][d] = base[C_ / 2];
        }
        __syncthreads();

        #pragma unroll 2
        for (int j = 0; j < MB; j++) {
            float2 s2 = make_float2(0.f, 0.f);
            #pragma unroll
            for (int d = 0; d < HD2_; d++) s2 = ffma2(qv[d], sK[j][d], s2);
            float s = s2.x + s2.y;                 // already in log2 domain
            if (s > mrun) {                        // rare after warmup
                float corr = exp2f(mrun - s);
                l *= corr;
                float2 c2 = make_float2(corr, corr);
                float2 z2 = make_float2(0.f, 0.f);
                #pragma unroll
                for (int d = 0; d < HD2_; d++) acc[d] = ffma2(acc[d], c2, z2);
                mrun = s;
            }
            float p = exp2f(s - mrun);
            l += p;
            float2 p2 = make_float2(p, p);
            #pragma unroll
            for (int d = 0; d < HD2_; d++) acc[d] = ffma2(p2, sV[j][d], acc[d]);
        }
        __syncthreads();
    }

    const float inv = 1.0f / l;
    float2* xp = reinterpret_cast<float2*>(x + ((size_t)(b * N_ + n)) * C_ + h * HD_);
    #pragma unroll
    for (int d = 0; d < HD2_; d++)
        xp[d] = make_float2(acc[d].x * inv, acc[d].y * inv);
}

// ---------------------------------------------------------------------------
// Launch
// ---------------------------------------------------------------------------
extern "C" void kernel_launch(void* const* d_in, const int* in_sizes, int n_in,
                              void* d_out, int out_size)
{
    const float* q_x   = (const float*)d_in[0];  // [4,4096,384]
    const float* kv_x  = (const float*)d_in[1];  // [4,1024,384]
    const float* Wq    = (const float*)d_in[2];  // [384,384]
    const float* Wkv   = (const float*)d_in[3];  // [384,768]
    const float* Wproj = (const float*)d_in[4];  // [384,384]
    const float* bproj = (const float*)d_in[5];  // [384]
    float* out = (float*)d_out;                  // [4,4096,384]

    float *gq, *gkv, *gx;
    cudaGetSymbolAddress((void**)&gq,  g_q);
    cudaGetSymbolAddress((void**)&gkv, g_kv);
    cudaGetSymbolAddress((void**)&gx,  g_x);

    // 1) q = q_x @ Wq          [16384,384]
    sgemm128_kernel<false><<<dim3(C_ / 128, (B_ * N_) / 128), 256>>>(
        q_x, Wq, gq, B_ * N_, C_, C_, nullptr, nullptr);

    // 2) kv = kv_x @ Wkv       [4096,768]
    sgemm128_kernel<false><<<dim3((2 * C_) / 128, (B_ * M_) / 128), 256>>>(
        kv_x, Wkv, gkv, B_ * M_, 2 * C_, C_, nullptr, nullptr);

    // 3) attention -> g_x [B,N,384]
    attn_kernel<<<dim3(N_ / 128, H_, B_), 128>>>(gq, gkv, gx);

    // 4) out = g_x @ Wproj + bproj + g_q
    sgemm128_kernel<true><<<dim3(C_ / 128, (B_ * N_) / 128), 256>>>(
        gx, Wproj, out, B_ * N_, C_, C_, bproj, gq);
}